// round 1
// baseline (speedup 1.0000x reference)
#include <cuda_runtime.h>
#include <math.h>

#define BATCH 16
#define SEQ   2048
#define DIM   128
#define MTOT  (BATCH * SEQ)

// Scratch (allocation-free: device globals)
__device__ float g_h [MTOT * DIM];
__device__ float g_a [MTOT * DIM];
__device__ float g_z [MTOT * DIM];
__device__ float g_ro[MTOT * DIM];

__device__ __forceinline__ float sigmoidf_(float v) {
    return 1.0f / (1.0f + __expf(-v));
}

// ---------------------------------------------------------------------------
// Dense GEMM over flattened rows: C[64 x 128] tile per block.
// C = epilogue( A1 @ W1 (+ A2 @ W2) + bias )
// MODE 0: relu(pre + b1)                          (encode)
// MODE 1: sigmoid(pre + b1 + b2)                  (z gate)
// MODE 2: sigmoid(pre + b1 + b2) * E1             (r gate * h  -> ro)
// MODE 3: relu(pre + b1 + b2)*E2 + E1*(1 - E2)    (GRU combine, E1=h, E2=z)
// ---------------------------------------------------------------------------
template<int MODE, bool DUAL>
__global__ void __launch_bounds__(256)
gemm128_kernel(const float* __restrict__ A1, const float* __restrict__ W1,
               const float* __restrict__ A2, const float* __restrict__ W2,
               const float* __restrict__ b1, const float* __restrict__ b2,
               const float* __restrict__ E1, const float* __restrict__ E2,
               float* __restrict__ Cout)
{
    __shared__ float As[16][64];    // k-major A tile
    __shared__ float Ws[16][128];   // k-major W tile

    const int tid  = threadIdx.x;
    const int tx   = tid & 15;      // col group: cols tx*8 .. tx*8+7
    const int ty   = tid >> 4;      // row group: rows ty*4 .. ty*4+3
    const int row0 = blockIdx.x * 64;

    float acc[4][8];
#pragma unroll
    for (int i = 0; i < 4; i++)
#pragma unroll
        for (int j = 0; j < 8; j++) acc[i][j] = 0.0f;

    const int ar = tid >> 2;          // A tile row 0..63
    const int ac = (tid & 3) * 4;     // A tile k offset 0/4/8/12
    const int wr = tid >> 5;          // W tile k row 0..7 (+8 for second)
    const int wc = (tid & 31) * 4;    // W tile col 0..124

#pragma unroll
    for (int seg = 0; seg < (DUAL ? 2 : 1); ++seg) {
        const float* __restrict__ A = seg ? A2 : A1;
        const float* __restrict__ W = seg ? W2 : W1;
#pragma unroll 1
        for (int k0 = 0; k0 < DIM; k0 += 16) {
            float4 av  = *(const float4*)(A + (size_t)(row0 + ar) * DIM + k0 + ac);
            float4 wv0 = *(const float4*)(W + (size_t)(k0 + wr)     * DIM + wc);
            float4 wv1 = *(const float4*)(W + (size_t)(k0 + wr + 8) * DIM + wc);
            __syncthreads();
            As[ac + 0][ar] = av.x;
            As[ac + 1][ar] = av.y;
            As[ac + 2][ar] = av.z;
            As[ac + 3][ar] = av.w;
            *(float4*)&Ws[wr][wc]     = wv0;
            *(float4*)&Ws[wr + 8][wc] = wv1;
            __syncthreads();
#pragma unroll
            for (int kk = 0; kk < 16; kk++) {
                const float4 a4 = *(const float4*)&As[kk][ty * 4];
                const float4 w0 = *(const float4*)&Ws[kk][tx * 8];
                const float4 w1 = *(const float4*)&Ws[kk][tx * 8 + 4];
                const float a_[4] = {a4.x, a4.y, a4.z, a4.w};
                const float w_[8] = {w0.x, w0.y, w0.z, w0.w, w1.x, w1.y, w1.z, w1.w};
#pragma unroll
                for (int i = 0; i < 4; i++)
#pragma unroll
                    for (int j = 0; j < 8; j++)
                        acc[i][j] = fmaf(a_[i], w_[j], acc[i][j]);
            }
        }
    }

    // Epilogue
    const int colb = tx * 8;
    float bias[8];
#pragma unroll
    for (int j = 0; j < 8; j++)
        bias[j] = b1[colb + j] + (DUAL ? b2[colb + j] : 0.0f);

#pragma unroll
    for (int i = 0; i < 4; i++) {
        const size_t base = (size_t)(row0 + ty * 4 + i) * DIM + colb;
        float out[8];
#pragma unroll
        for (int j = 0; j < 8; j++) {
            float v = acc[i][j] + bias[j];
            if (MODE == 0) {
                v = fmaxf(v, 0.0f);
            } else if (MODE == 1) {
                v = sigmoidf_(v);
            } else if (MODE == 2) {
                v = sigmoidf_(v) * E1[base + j];
            } else {
                const float zz = E2[base + j];
                const float hp = E1[base + j];
                v = fmaxf(v, 0.0f) * zz + hp * (1.0f - zz);
            }
            out[j] = v;
        }
        *(float4*)(Cout + base)     = make_float4(out[0], out[1], out[2], out[3]);
        *(float4*)(Cout + base + 4) = make_float4(out[4], out[5], out[6], out[7]);
    }
}

// ---------------------------------------------------------------------------
// a[b, row, :] = (sum_k support[b,row,k] * h[b,k,:]) * (1 + FFD[b,row])
// Per-block tile: 64 rows x 128 cols, K = 2048 in chunks of 16.
// ---------------------------------------------------------------------------
__global__ void __launch_bounds__(256)
spmm_kernel(const float* __restrict__ S, const float* __restrict__ H,
            const float* __restrict__ ffd, float* __restrict__ Aout)
{
    __shared__ float Ss[16][64];
    __shared__ float Hs[16][128];

    const int tid  = threadIdx.x;
    const int tx   = tid & 15;
    const int ty   = tid >> 4;
    const int b    = blockIdx.y;
    const int row0 = blockIdx.x * 64;

    const float* __restrict__ Sb = S + (size_t)b * SEQ * SEQ;
    const float* __restrict__ Hb = H + (size_t)b * SEQ * DIM;

    float acc[4][8];
#pragma unroll
    for (int i = 0; i < 4; i++)
#pragma unroll
        for (int j = 0; j < 8; j++) acc[i][j] = 0.0f;

    const int ar = tid >> 2;
    const int ac = (tid & 3) * 4;
    const int wr = tid >> 5;
    const int wc = (tid & 31) * 4;

#pragma unroll 1
    for (int k0 = 0; k0 < SEQ; k0 += 16) {
        float4 sv  = *(const float4*)(Sb + (size_t)(row0 + ar) * SEQ + k0 + ac);
        float4 hv0 = *(const float4*)(Hb + (size_t)(k0 + wr)     * DIM + wc);
        float4 hv1 = *(const float4*)(Hb + (size_t)(k0 + wr + 8) * DIM + wc);
        __syncthreads();
        Ss[ac + 0][ar] = sv.x;
        Ss[ac + 1][ar] = sv.y;
        Ss[ac + 2][ar] = sv.z;
        Ss[ac + 3][ar] = sv.w;
        *(float4*)&Hs[wr][wc]     = hv0;
        *(float4*)&Hs[wr + 8][wc] = hv1;
        __syncthreads();
#pragma unroll
        for (int kk = 0; kk < 16; kk++) {
            const float4 a4 = *(const float4*)&Ss[kk][ty * 4];
            const float4 w0 = *(const float4*)&Hs[kk][tx * 8];
            const float4 w1 = *(const float4*)&Hs[kk][tx * 8 + 4];
            const float a_[4] = {a4.x, a4.y, a4.z, a4.w};
            const float w_[8] = {w0.x, w0.y, w0.z, w0.w, w1.x, w1.y, w1.z, w1.w};
#pragma unroll
            for (int i = 0; i < 4; i++)
#pragma unroll
                for (int j = 0; j < 8; j++)
                    acc[i][j] = fmaf(a_[i], w_[j], acc[i][j]);
        }
    }

    const float* __restrict__ ffdb = ffd + (size_t)b * SEQ;
    float* __restrict__ Ab = Aout + (size_t)b * SEQ * DIM;
#pragma unroll
    for (int i = 0; i < 4; i++) {
        const int row = row0 + ty * 4 + i;
        const float scale = 1.0f + ffdb[row];
        const size_t base = (size_t)row * DIM + tx * 8;
        *(float4*)(Ab + base)     = make_float4(acc[i][0] * scale, acc[i][1] * scale,
                                                acc[i][2] * scale, acc[i][3] * scale);
        *(float4*)(Ab + base + 4) = make_float4(acc[i][4] * scale, acc[i][5] * scale,
                                                acc[i][6] * scale, acc[i][7] * scale);
    }
}

extern "C" void kernel_launch(void* const* d_in, const int* in_sizes, int n_in,
                              void* d_out, int out_size)
{
    const float* x       = (const float*)d_in[0];
    const float* support = (const float*)d_in[1];
    const float* ffd     = (const float*)d_in[2];
    // d_in[3] = mask (unused by reference)
    const float* We  = (const float*)d_in[4];
    const float* be  = (const float*)d_in[5];
    const float* Wz0 = (const float*)d_in[6];
    const float* bz0 = (const float*)d_in[7];
    const float* Wz1 = (const float*)d_in[8];
    const float* bz1 = (const float*)d_in[9];
    const float* Wr0 = (const float*)d_in[10];
    const float* br0 = (const float*)d_in[11];
    const float* Wr1 = (const float*)d_in[12];
    const float* br1 = (const float*)d_in[13];
    const float* Wh0 = (const float*)d_in[14];
    const float* bh0 = (const float*)d_in[15];
    const float* Wh1 = (const float*)d_in[16];
    const float* bh1 = (const float*)d_in[17];

    float *h, *a, *z, *ro;
    cudaGetSymbolAddress((void**)&h,  g_h);
    cudaGetSymbolAddress((void**)&a,  g_a);
    cudaGetSymbolAddress((void**)&z,  g_z);
    cudaGetSymbolAddress((void**)&ro, g_ro);

    const dim3 blk(256);
    const dim3 grd_dense(MTOT / 64);
    const dim3 grd_spmm(SEQ / 64, BATCH);

    // h = relu(x @ We + be)
    gemm128_kernel<0, false><<<grd_dense, blk>>>(x, We, nullptr, nullptr,
                                                 be, nullptr, nullptr, nullptr, h);

    for (int t = 0; t < 2; ++t) {
        // a = (support @ h) * (1 + FFD)
        spmm_kernel<<<grd_spmm, blk>>>(support, h, ffd, a);
        // z = sigmoid(a@Wz0 + h@Wz1 + bz0 + bz1)
        gemm128_kernel<1, true><<<grd_dense, blk>>>(a, Wz0, h, Wz1,
                                                    bz0, bz1, nullptr, nullptr, z);
        // ro = sigmoid(a@Wr0 + h@Wr1 + br0 + br1) * h
        gemm128_kernel<2, true><<<grd_dense, blk>>>(a, Wr0, h, Wr1,
                                                    br0, br1, h, nullptr, ro);
        // h' = relu(a@Wh0 + ro@Wh1 + bh0 + bh1)*z + h*(1-z)
        float* dst = (t == 1) ? (float*)d_out : h;
        gemm128_kernel<3, true><<<grd_dense, blk>>>(a, Wh0, ro, Wh1,
                                                    bh0, bh1, h, z, dst);
    }
}

// round 4
// speedup vs baseline: 2.1034x; 2.1034x over previous
#include <cuda_runtime.h>
#include <math.h>
#include <stdint.h>

#define BATCH 16
#define SEQ   2048
#define DIM   128
#define MTOT  (BATCH * SEQ)

// ---------------- scratch (allocation-free device globals) ----------------
__device__ float g_h [MTOT * DIM];   // h   (exact fp32)
__device__ float g_a [MTOT * DIM];   // a   (exact fp32)
__device__ float g_z [MTOT * DIM];   // z   (exact fp32)
__device__ float g_ro[MTOT * DIM];   // r*h (exact fp32)

__device__ __forceinline__ float sigmoidf_(float v) {
    return 1.0f / (1.0f + __expf(-v));
}
__device__ __forceinline__ uint32_t smem_u32(const void* p) {
    uint32_t a;
    asm("{ .reg .u64 t; cvta.to.shared.u64 t, %1; cvt.u32.u64 %0, t; }" : "=r"(a) : "l"(p));
    return a;
}
__device__ __forceinline__ uint32_t cvt_tf32(float x) {
    uint32_t u;
    asm("cvt.rna.tf32.f32 %0, %1;" : "=r"(u) : "f"(x));
    return u;
}
// split x into hi (tf32) + lo (tf32 of residual); hi+lo ~ x to ~2^-22
__device__ __forceinline__ void split_tf32(float x, uint32_t& hi, uint32_t& lo) {
    hi = cvt_tf32(x);
    lo = cvt_tf32(x - __uint_as_float(hi));
}
__device__ __forceinline__ void cp16(uint32_t dst, const float* src) {
    asm volatile("cp.async.cg.shared.global [%0], [%1], 16;" :: "r"(dst), "l"(src));
}
__device__ __forceinline__ void mma_tf32(float* d, const uint32_t* a,
                                         uint32_t b0, uint32_t b1) {
    asm volatile("mma.sync.aligned.m16n8k8.row.col.f32.tf32.tf32.f32 "
                 "{%0,%1,%2,%3}, {%4,%5,%6,%7}, {%8,%9}, {%0,%1,%2,%3};"
                 : "+f"(d[0]), "+f"(d[1]), "+f"(d[2]), "+f"(d[3])
                 : "r"(a[0]), "r"(a[1]), "r"(a[2]), "r"(a[3]), "r"(b0), "r"(b1));
}

// smem layout (floats): A bufs [2][128][36], then B bufs [2][32][132]
#define APITCH 36
#define BPITCH 132
#define ABUF   (128 * APITCH)
#define BBUF   (32 * BPITCH)
#define SMEMF  (2 * ABUF + 2 * BBUF)     // 17664 floats = 70656 B

// ---------------------------------------------------------------------------
// 3xTF32 tensor-core GEMM (fp32-class accuracy), 128x128 tile / 256 threads.
// C = epilogue( A1 @ B1 (+ A2 @ B2) + bias )
// MODE 0: relu(v + b1)
// MODE 1: sigmoid(v + b1 + b2)
// MODE 2: sigmoid(v + b1 + b2) * E1
// MODE 3: relu(v + b1 + b2)*E2 + E1*(1-E2)
// MODE 4: v * (1 + ffd[row])                      (spmm)
// ---------------------------------------------------------------------------
template<int MODE, bool DUAL, bool SPMM, int K>
__global__ void __launch_bounds__(256, 2)
gemm_tc(const float* __restrict__ A1g, const float* __restrict__ B1g,
        const float* __restrict__ A2g, const float* __restrict__ B2g,
        const float* __restrict__ bias1, const float* __restrict__ bias2,
        const float* __restrict__ E1, const float* __restrict__ E2,
        const float* __restrict__ ffd,
        float* __restrict__ Cout)
{
    extern __shared__ float smem[];
    const uint32_t sbase = smem_u32(smem);

    const int tid   = threadIdx.x;
    const int lane  = tid & 31;
    const int warp  = tid >> 5;
    const int wm    = warp & 3;
    const int wn    = warp >> 2;
    const int mbase = wm * 32;
    const int nbase = wn * 64;
    const int lq    = lane >> 2;      // 0..7
    const int lt    = lane & 3;       // 0..3

    const size_t rowTile = SPMM ? ((size_t)blockIdx.y * SEQ + (size_t)blockIdx.x * 128)
                                : ((size_t)blockIdx.x * 128);
    const size_t LDA   = SPMM ? SEQ : 128;
    const size_t kBase = SPMM ? (size_t)blockIdx.y * SEQ : 0;

    constexpr int KCH = K / 32;
    constexpr int NC  = DUAL ? 2 * KCH : KCH;

    float acc[2][8][4];
#pragma unroll
    for (int mi = 0; mi < 2; mi++)
#pragma unroll
        for (int j = 0; j < 8; j++)
#pragma unroll
            for (int q = 0; q < 4; q++) acc[mi][j][q] = 0.0f;

    auto issue = [&](int c, int buf) {
        const bool  seg = DUAL && (c >= KCH);
        const float* __restrict__ A = seg ? A2g : A1g;
        const float* __restrict__ B = seg ? B2g : B1g;
        const int k0 = (seg ? c - KCH : c) * 32;
#pragma unroll
        for (int i = 0; i < 4; i++) {
            const int idx = tid + i * 256;
            const int r = idx >> 3, g = idx & 7;
            cp16(sbase + (uint32_t)(buf * ABUF + r * APITCH + g * 4) * 4,
                 A + (rowTile + r) * LDA + k0 + g * 4);
        }
#pragma unroll
        for (int i = 0; i < 4; i++) {
            const int idx = tid + i * 256;
            const int r = idx >> 5, g = idx & 31;
            cp16(sbase + (uint32_t)(2 * ABUF + buf * BBUF + r * BPITCH + g * 4) * 4,
                 B + (kBase + k0 + r) * 128 + g * 4);
        }
        asm volatile("cp.async.commit_group;");
    };

    issue(0, 0);

#pragma unroll 1
    for (int c = 0; c < NC; ++c) {
        const int buf = c & 1;
        if (c + 1 < NC) {
            issue(c + 1, buf ^ 1);
            asm volatile("cp.async.wait_group 1;");
        } else {
            asm volatile("cp.async.wait_group 0;");
        }
        __syncthreads();

        const float* __restrict__ Ab = smem + buf * ABUF;
        const float* __restrict__ Bb = smem + 2 * ABUF + buf * BBUF;

#pragma unroll
        for (int kk = 0; kk < 32; kk += 8) {
            // A fragments, split hi/lo
            uint32_t ah[2][4], al[2][4];
#pragma unroll
            for (int mi = 0; mi < 2; mi++) {
                const int m0 = mbase + mi * 16;
                split_tf32(Ab[(m0 +     lq) * APITCH + kk +     lt], ah[mi][0], al[mi][0]);
                split_tf32(Ab[(m0 + 8 + lq) * APITCH + kk +     lt], ah[mi][1], al[mi][1]);
                split_tf32(Ab[(m0 +     lq) * APITCH + kk + 4 + lt], ah[mi][2], al[mi][2]);
                split_tf32(Ab[(m0 + 8 + lq) * APITCH + kk + 4 + lt], ah[mi][3], al[mi][3]);
            }
#pragma unroll
            for (int j = 0; j < 8; j++) {
                const int n = nbase + j * 8 + lq;
                uint32_t bh0, bl0, bh1, bl1;
                split_tf32(Bb[(kk +     lt) * BPITCH + n], bh0, bl0);
                split_tf32(Bb[(kk + 4 + lt) * BPITCH + n], bh1, bl1);
#pragma unroll
                for (int mi = 0; mi < 2; mi++) {
                    mma_tf32(acc[mi][j], ah[mi], bh0, bh1);   // hi*hi
                    mma_tf32(acc[mi][j], ah[mi], bl0, bl1);   // hi*lo
                    mma_tf32(acc[mi][j], al[mi], bh0, bh1);   // lo*hi
                }
            }
        }
        __syncthreads();
    }

    // ---- epilogue ----
#pragma unroll
    for (int mi = 0; mi < 2; mi++) {
        const int rA = mbase + mi * 16 + lq;
        const size_t gr0 = rowTile + rA;
        const size_t gr1 = gr0 + 8;
        float s0 = 1.0f, s1 = 1.0f;
        if (MODE == 4) { s0 += ffd[gr0]; s1 += ffd[gr1]; }

#pragma unroll
        for (int j = 0; j < 8; j++) {
            const int col = nbase + j * 8 + lt * 2;
            float o[4];
#pragma unroll
            for (int q = 0; q < 4; q++) {
                const int    cc = col + (q & 1);
                const size_t gr = (q < 2) ? gr0 : gr1;
                float v = acc[mi][j][q];
                if (MODE == 0) {
                    v = fmaxf(v + bias1[cc], 0.0f);
                } else if (MODE == 1) {
                    v = sigmoidf_(v + bias1[cc] + bias2[cc]);
                } else if (MODE == 2) {
                    v = sigmoidf_(v + bias1[cc] + bias2[cc]) * E1[gr * 128 + cc];
                } else if (MODE == 3) {
                    const float zz = E2[gr * 128 + cc];
                    const float hp = E1[gr * 128 + cc];
                    v = fmaxf(v + bias1[cc] + bias2[cc], 0.0f) * zz + hp * (1.0f - zz);
                } else {
                    v = v * ((q < 2) ? s0 : s1);
                }
                o[q] = v;
            }
            *(float2*)&Cout[gr0 * 128 + col] = make_float2(o[0], o[1]);
            *(float2*)&Cout[gr1 * 128 + col] = make_float2(o[2], o[3]);
        }
    }
}

extern "C" void kernel_launch(void* const* d_in, const int* in_sizes, int n_in,
                              void* d_out, int out_size)
{
    const float* x       = (const float*)d_in[0];
    const float* support = (const float*)d_in[1];
    const float* ffd     = (const float*)d_in[2];
    // d_in[3] = mask (unused by reference)
    const float* We  = (const float*)d_in[4];
    const float* be  = (const float*)d_in[5];
    const float* Wz0 = (const float*)d_in[6];
    const float* bz0 = (const float*)d_in[7];
    const float* Wz1 = (const float*)d_in[8];
    const float* bz1 = (const float*)d_in[9];
    const float* Wr0 = (const float*)d_in[10];
    const float* br0 = (const float*)d_in[11];
    const float* Wr1 = (const float*)d_in[12];
    const float* br1 = (const float*)d_in[13];
    const float* Wh0 = (const float*)d_in[14];
    const float* bh0 = (const float*)d_in[15];
    const float* Wh1 = (const float*)d_in[16];
    const float* bh1 = (const float*)d_in[17];

    float *h, *a, *z, *ro;
    cudaGetSymbolAddress((void**)&h,  g_h);
    cudaGetSymbolAddress((void**)&a,  g_a);
    cudaGetSymbolAddress((void**)&z,  g_z);
    cudaGetSymbolAddress((void**)&ro, g_ro);

    const int SMB = SMEMF * 4;
    cudaFuncSetAttribute(gemm_tc<0, false, false, 128>, cudaFuncAttributeMaxDynamicSharedMemorySize, SMB);
    cudaFuncSetAttribute(gemm_tc<1, true,  false, 128>, cudaFuncAttributeMaxDynamicSharedMemorySize, SMB);
    cudaFuncSetAttribute(gemm_tc<2, true,  false, 128>, cudaFuncAttributeMaxDynamicSharedMemorySize, SMB);
    cudaFuncSetAttribute(gemm_tc<3, true,  false, 128>, cudaFuncAttributeMaxDynamicSharedMemorySize, SMB);
    cudaFuncSetAttribute(gemm_tc<4, false, true, 2048>, cudaFuncAttributeMaxDynamicSharedMemorySize, SMB);

    const dim3 blk(256);
    const dim3 grd_dense(MTOT / 128);          // 256
    const dim3 grd_spmm(SEQ / 128, BATCH);     // (16,16)

    // h = relu(x @ We + be)
    gemm_tc<0, false, false, 128><<<grd_dense, blk, SMB>>>(
        x, We, nullptr, nullptr, be, nullptr, nullptr, nullptr, nullptr, h);

    for (int t = 0; t < 2; ++t) {
        // a = (support @ h) * (1 + FFD)
        gemm_tc<4, false, true, 2048><<<grd_spmm, blk, SMB>>>(
            support, h, nullptr, nullptr, nullptr, nullptr, nullptr, nullptr, ffd, a);
        // z = sigmoid(a@Wz0 + h@Wz1 + bz)
        gemm_tc<1, true, false, 128><<<grd_dense, blk, SMB>>>(
            a, Wz0, h, Wz1, bz0, bz1, nullptr, nullptr, nullptr, z);
        // ro = sigmoid(a@Wr0 + h@Wr1 + br) * h
        gemm_tc<2, true, false, 128><<<grd_dense, blk, SMB>>>(
            a, Wr0, h, Wr1, br0, br1, h, nullptr, nullptr, ro);
        // h' = relu(a@Wh0 + ro@Wh1 + bh)*z + h*(1-z)
        float* dst = (t == 1) ? (float*)d_out : h;
        gemm_tc<3, true, false, 128><<<grd_dense, blk, SMB>>>(
            a, Wh0, ro, Wh1, bh0, bh1, h, z, nullptr, dst);
    }
}